// round 2
// baseline (speedup 1.0000x reference)
#include <cuda_runtime.h>
#include <cuda_bf16.h>

// RBF causal attention: out_i = sum_{j<=i} exp(2s*q.k - s|q|^2 - s|k|^2) v_j
// B=2, H=16, S=2048, D=64, fp32.

#define B_  2
#define H_  16
#define S_  2048
#define D_  64
#define SCALE 0.125f

#define BM 128      // query tile rows
#define BN 128      // key tile rows
#define NT 256      // threads per block
#define QS 65       // padded f32 stride for Q/K/V tiles (conflict-free)
#define PS 144      // padded f32 stride for P tile (disjoint half-warp banks)

#define SMEM_FLOATS (3 * BM * QS + BM * PS + 2 * BM)

__global__ __launch_bounds__(NT, 1)
void rbf_attn_kernel(const float* __restrict__ q,
                     const float* __restrict__ k,
                     const float* __restrict__ v,
                     float* __restrict__ out) {
    extern __shared__ float sm[];
    float* Qs  = sm;                 // [BM][QS]
    float* Ks  = Qs + BM * QS;       // [BN][QS]
    float* Vs  = Ks + BM * QS;       // [BN][QS]
    float* Ps  = Vs + BM * QS;       // [BM][PS]
    float* qsq = Ps + BM * PS;       // [BM]
    float* ksq = qsq + BM;           // [BN]

    const int bh  = blockIdx.y;
    const int qt  = (int)gridDim.x - 1 - (int)blockIdx.x;  // heavy tiles first
    const int tid = threadIdx.x;
    const int tx  = tid & 15;        // 16 column groups
    const int ty  = tid >> 4;        // 16 row groups
    const size_t base = (size_t)bh * S_ * D_;

    // ---- Load Q tile (coalesced float4) ----
    {
        const float4* g = (const float4*)(q + base + (size_t)qt * BM * D_);
        #pragma unroll
        for (int r = 0; r < 8; r++) {
            int idx = tid + NT * r;          // 0..2047 float4s
            float4 a = g[idx];
            int row = idx >> 4, c = (idx & 15) << 2;
            float* d = &Qs[row * QS + c];
            d[0] = a.x; d[1] = a.y; d[2] = a.z; d[3] = a.w;
        }
    }
    __syncthreads();
    if (tid < BM) {
        float s = 0.f;
        #pragma unroll
        for (int d = 0; d < D_; d++) { float x = Qs[tid * QS + d]; s = fmaf(x, x, s); }
        qsq[tid] = s * SCALE;
    }

    float acc_o[8][4];
    #pragma unroll
    for (int i = 0; i < 8; i++)
        #pragma unroll
        for (int j = 0; j < 4; j++) acc_o[i][j] = 0.f;

    for (int kt = 0; kt <= qt; kt++) {
        __syncthreads();   // guards K/V/P reuse from previous iteration (and qsq on iter 0)

        // ---- Load K,V tiles ----
        {
            const float4* gk = (const float4*)(k + base + (size_t)kt * BN * D_);
            const float4* gv = (const float4*)(v + base + (size_t)kt * BN * D_);
            #pragma unroll
            for (int r = 0; r < 8; r++) {
                int idx = tid + NT * r;
                int row = idx >> 4, c = (idx & 15) << 2;
                float4 a = gk[idx];
                float* dk = &Ks[row * QS + c];
                dk[0] = a.x; dk[1] = a.y; dk[2] = a.z; dk[3] = a.w;
                float4 b = gv[idx];
                float* dv = &Vs[row * QS + c];
                dv[0] = b.x; dv[1] = b.y; dv[2] = b.z; dv[3] = b.w;
            }
        }
        __syncthreads();
        if (tid < BN) {
            float s = 0.f;
            #pragma unroll
            for (int d = 0; d < D_; d++) { float x = Ks[tid * QS + d]; s = fmaf(x, x, s); }
            ksq[tid] = s * SCALE;
        }
        __syncthreads();

        // ---- S = Q K^T (128x128, 8x8 per thread, interleaved mapping) ----
        float accs[8][8];
        #pragma unroll
        for (int i = 0; i < 8; i++)
            #pragma unroll
            for (int j = 0; j < 8; j++) accs[i][j] = 0.f;

        #pragma unroll 4
        for (int d = 0; d < D_; d++) {
            float rq[8], rk[8];
            #pragma unroll
            for (int i = 0; i < 8; i++) rq[i] = Qs[(ty + 16 * i) * QS + d];
            #pragma unroll
            for (int j = 0; j < 8; j++) rk[j] = Ks[(tx + 16 * j) * QS + d];
            #pragma unroll
            for (int i = 0; i < 8; i++)
                #pragma unroll
                for (int j = 0; j < 8; j++)
                    accs[i][j] = fmaf(rq[i], rk[j], accs[i][j]);
        }

        // ---- P = exp(2s*S - qsq - ksq), causal mask on diagonal tile ----
        const bool diag = (kt == qt);
        #pragma unroll
        for (int i = 0; i < 8; i++) {
            const int m = ty + 16 * i;
            const float qm = qsq[m];
            #pragma unroll
            for (int j = 0; j < 8; j++) {
                const int n = tx + 16 * j;
                float l = fmaf(2.f * SCALE, accs[i][j], -(qm + ksq[n]));
                float p = __expf(l);
                if (diag && (n > m)) p = 0.f;
                Ps[m * PS + n] = p;
            }
        }
        __syncthreads();

        // ---- O += P V (128x64, 8x4 per thread) ----
        #pragma unroll 4
        for (int n = 0; n < BN; n++) {
            float rv[4], rp[8];
            #pragma unroll
            for (int jd = 0; jd < 4; jd++) rv[jd] = Vs[n * QS + tx + 16 * jd];
            #pragma unroll
            for (int i = 0; i < 8; i++) rp[i] = Ps[(ty + 16 * i) * PS + n];
            #pragma unroll
            for (int i = 0; i < 8; i++)
                #pragma unroll
                for (int jd = 0; jd < 4; jd++)
                    acc_o[i][jd] = fmaf(rp[i], rv[jd], acc_o[i][jd]);
        }
    }

    // ---- Write output ----
    float* og = out + base + (size_t)qt * BM * D_;
    #pragma unroll
    for (int i = 0; i < 8; i++)
        #pragma unroll
        for (int jd = 0; jd < 4; jd++)
            og[(ty + 16 * i) * D_ + tx + 16 * jd] = acc_o[i][jd];
}

extern "C" void kernel_launch(void* const* d_in, const int* in_sizes, int n_in,
                              void* d_out, int out_size) {
    const float* q = (const float*)d_in[0];
    const float* k = (const float*)d_in[1];
    const float* v = (const float*)d_in[2];
    float* out = (float*)d_out;

    size_t smem = (size_t)SMEM_FLOATS * sizeof(float);
    cudaFuncSetAttribute(rbf_attn_kernel,
                         cudaFuncAttributeMaxDynamicSharedMemorySize, (int)smem);
    dim3 grid(S_ / BM, B_ * H_);
    rbf_attn_kernel<<<grid, NT, smem>>>(q, k, v, out);
}

// round 5
// speedup vs baseline: 5.4217x; 5.4217x over previous
#include <cuda_runtime.h>
#include <cuda_bf16.h>
#include <cstdint>

// RBF causal attention via mma.sync (HMMA) bf16 split-precision.
// B=2, H=16, S=2048, D=64, fp32 in/out.

#define B_ 2
#define H_ 16
#define S_ 2048
#define D_ 64
#define SCALE 0.125f
#define NBHS (B_*H_*S_)
#define NBHSD2 (NBHS*32)        // bf16x2 elems (D/2 = 32 per row)

// ---- scratch (static device globals; no runtime alloc) ----
__device__ __nv_bfloat162 g_qhi[NBHSD2];
__device__ __nv_bfloat162 g_qlo[NBHSD2];
__device__ __nv_bfloat162 g_khi[NBHSD2];
__device__ __nv_bfloat162 g_klo[NBHSD2];
__device__ __nv_bfloat162 g_vhi[NBHSD2];
__device__ __nv_bfloat162 g_vlo[NBHSD2];
__device__ float g_qsq[NBHS];
__device__ float g_ksq[NBHS];

// ============================ helpers ============================
__device__ __forceinline__ uint32_t smem_u32(const void* p) {
    uint32_t a;
    asm("{ .reg .u64 t; cvta.to.shared.u64 t, %1; cvt.u32.u64 %0, t; }" : "=r"(a) : "l"(p));
    return a;
}
__device__ __forceinline__ void cp16(uint32_t s, const void* g) {
    asm volatile("cp.async.cg.shared.global [%0], [%1], 16;\n" :: "r"(s), "l"(g));
}
#define CP_COMMIT() asm volatile("cp.async.commit_group;\n" ::: "memory")
template <int N>
__device__ __forceinline__ void cp_wait() {
    asm volatile("cp.async.wait_group %0;\n" :: "n"(N) : "memory");
}
__device__ __forceinline__ void ldsm4(uint32_t r[4], uint32_t a) {
    asm volatile("ldmatrix.sync.aligned.m8n8.x4.shared.b16 {%0,%1,%2,%3}, [%4];\n"
        : "=r"(r[0]), "=r"(r[1]), "=r"(r[2]), "=r"(r[3]) : "r"(a));
}
__device__ __forceinline__ void ldsm4t(uint32_t r[4], uint32_t a) {
    asm volatile("ldmatrix.sync.aligned.m8n8.x4.trans.shared.b16 {%0,%1,%2,%3}, [%4];\n"
        : "=r"(r[0]), "=r"(r[1]), "=r"(r[2]), "=r"(r[3]) : "r"(a));
}
__device__ __forceinline__ void mma_bf16(float c[4], const uint32_t a[4],
                                         uint32_t b0, uint32_t b1) {
    asm volatile("mma.sync.aligned.m16n8k16.row.col.f32.bf16.bf16.f32 "
        "{%0,%1,%2,%3}, {%4,%5,%6,%7}, {%8,%9}, {%0,%1,%2,%3};\n"
        : "+f"(c[0]), "+f"(c[1]), "+f"(c[2]), "+f"(c[3])
        : "r"(a[0]), "r"(a[1]), "r"(a[2]), "r"(a[3]), "r"(b0), "r"(b1));
}
__device__ __forceinline__ uint32_t b2u(__nv_bfloat162 h) {
    union { __nv_bfloat162 b; uint32_t u; } cv; cv.b = h; return cv.u;
}

// ============================ prepass ============================
__global__ __launch_bounds__(256)
void prep_kernel(const float* __restrict__ q, const float* __restrict__ k,
                 const float* __restrict__ v) {
    int r   = blockIdx.x * 8 + (threadIdx.x >> 5);
    int lid = threadIdx.x & 31;
    size_t e2 = (size_t)r * 32 + lid;

    float2 x = ((const float2*)q)[e2];
    __nv_bfloat162 h = __floats2bfloat162_rn(x.x, x.y);
    float2 hf = __bfloat1622float2(h);
    g_qhi[e2] = h;
    g_qlo[e2] = __floats2bfloat162_rn(x.x - hf.x, x.y - hf.y);
    float s = x.x * x.x + x.y * x.y;
    #pragma unroll
    for (int o = 16; o; o >>= 1) s += __shfl_xor_sync(0xffffffffu, s, o);
    if (!lid) g_qsq[r] = SCALE * s;

    x = ((const float2*)k)[e2];
    h = __floats2bfloat162_rn(x.x, x.y);
    hf = __bfloat1622float2(h);
    g_khi[e2] = h;
    g_klo[e2] = __floats2bfloat162_rn(x.x - hf.x, x.y - hf.y);
    s = x.x * x.x + x.y * x.y;
    #pragma unroll
    for (int o = 16; o; o >>= 1) s += __shfl_xor_sync(0xffffffffu, s, o);
    if (!lid) g_ksq[r] = SCALE * s;

    x = ((const float2*)v)[e2];
    h = __floats2bfloat162_rn(x.x, x.y);
    hf = __bfloat1622float2(h);
    g_vhi[e2] = h;
    g_vlo[e2] = __floats2bfloat162_rn(x.x - hf.x, x.y - hf.y);
}

// ============================ main kernel ============================
#define NT 256
#define OFF_Q   0              // Qhi 16KB, Qlo 16KB
#define OFF_KV  32768          // per buf: Khi,Klo,Vhi,Vlo (16KB each)
#define KVSTRIDE 65536
#define OFF_KSQ 163840         // 512B per buf x2
#define OFF_QSQ 164864         // 512B
#define SMEM_BYTES 165376

__global__ __launch_bounds__(NT, 1)
void rbf_mma_kernel(float* __restrict__ out) {
    extern __shared__ char smc[];
    const uint32_t smb = smem_u32(smc);
    const int tid = threadIdx.x, lane = tid & 31, warp = tid >> 5;
    const int bh = blockIdx.y;
    const int qt = (int)gridDim.x - 1 - (int)blockIdx.x;   // heavy tiles first
    const size_t row0q = (size_t)bh * S_ + (size_t)qt * 128;

    // ---- group 0: Q hi/lo + qsq + tile 0 K/V ----
    {
        const char* gq0 = (const char*)(g_qhi + row0q * 32);
        const char* gq1 = (const char*)(g_qlo + row0q * 32);
        #pragma unroll
        for (int i = 0; i < 4; i++) {
            int idx = tid + NT * i;              // 0..1023 16B chunks
            int row = idx >> 3, c = idx & 7;
            uint32_t rel = row * 128 + ((c ^ (row & 7)) << 4);
            cp16(smb + OFF_Q + rel, gq0 + idx * 16);
            cp16(smb + OFF_Q + 16384 + rel, gq1 + idx * 16);
        }
        if (tid < 32) cp16(smb + OFF_QSQ + tid * 16, g_qsq + row0q + tid * 4);
    }

    auto prefetch = [&](int kt2, int buf) {
        const size_t row0k = (size_t)bh * S_ + (size_t)kt2 * 128;
        const char* ga[4] = { (const char*)(g_khi + row0k * 32),
                              (const char*)(g_klo + row0k * 32),
                              (const char*)(g_vhi + row0k * 32),
                              (const char*)(g_vlo + row0k * 32) };
        const uint32_t bb = smb + OFF_KV + buf * KVSTRIDE;
        #pragma unroll
        for (int a = 0; a < 4; a++)
            #pragma unroll
            for (int i = 0; i < 4; i++) {
                int idx = tid + NT * i;
                int row = idx >> 3, c = idx & 7;
                cp16(bb + a * 16384 + row * 128 + ((c ^ (row & 7)) << 4), ga[a] + idx * 16);
            }
        if (tid < 32) cp16(smb + OFF_KSQ + buf * 512 + tid * 16, g_ksq + row0k + tid * 4);
    };

    prefetch(0, 0);
    CP_COMMIT();

    // per-thread fragment coordinates
    const int g8 = lane >> 2;                    // 0..7
    const int t2 = (lane & 3) * 2;               // 0,2,4,6
    const int arow = warp * 16 + (lane & 15);    // A (Q/P) ldmatrix row
    const int acb  = (lane >> 4) * 16;           // A k-byte half
    const int brow = (lane & 7) + (lane >> 4) * 8;       // K ldmatrix row offset
    const int bcb  = ((lane >> 3) & 1) * 16;             // K k-byte half
    const int vrow = (lane & 7) + ((lane >> 3) & 1) * 8; // V ldmatrix row offset
    const int vcb  = (lane >> 4) * 16;                   // V d-byte half

    uint32_t qh[4][4], ql[4][4];                 // Q frags, loaded at kt==0
    float co[8][4];
    #pragma unroll
    for (int i = 0; i < 8; i++) { co[i][0] = co[i][1] = co[i][2] = co[i][3] = 0.f; }

    const float* qsq_s = (const float*)(smc + OFF_QSQ);

    for (int kt = 0; kt <= qt; kt++) {
        const int buf = kt & 1;
        if (kt < qt) { prefetch(kt + 1, buf ^ 1); CP_COMMIT(); cp_wait<1>(); }
        else         { cp_wait<0>(); }
        __syncthreads();

        const uint32_t kvb  = smb + OFF_KV + buf * KVSTRIDE;
        const uint32_t khib = kvb;
        const uint32_t klob = kvb + 16384;
        const uint32_t vhib = kvb + 32768;
        const float* ksq_s = (const float*)(smc + OFF_KSQ + buf * 512);

        if (kt == 0) {
            #pragma unroll
            for (int kc = 0; kc < 4; kc++) {
                uint32_t kb = kc * 32 + acb;
                uint32_t addr = smb + OFF_Q + arow * 128 + ((((kb >> 4)) ^ (arow & 7)) << 4);
                ldsm4(qh[kc], addr);
                ldsm4(ql[kc], addr + 16384);
            }
        }

        // ---- S = Q K^T (3 split terms), warp stripe 16 x 128 ----
        float cs[16][4];
        #pragma unroll
        for (int i = 0; i < 16; i++) { cs[i][0] = cs[i][1] = cs[i][2] = cs[i][3] = 0.f; }

        #pragma unroll
        for (int kc = 0; kc < 4; kc++) {
            uint32_t kb = kc * 32 + bcb;
            #pragma unroll
            for (int nf2 = 0; nf2 < 8; nf2++) {
                int key = nf2 * 16 + brow;
                uint32_t rel = key * 128 + (((kb >> 4) ^ (key & 7)) << 4);
                uint32_t bk[4];
                ldsm4(bk, khib + rel);                       // Khi
                mma_bf16(cs[2 * nf2],     qh[kc], bk[0], bk[1]);
                mma_bf16(cs[2 * nf2 + 1], qh[kc], bk[2], bk[3]);
                mma_bf16(cs[2 * nf2],     ql[kc], bk[0], bk[1]);
                mma_bf16(cs[2 * nf2 + 1], ql[kc], bk[2], bk[3]);
                ldsm4(bk, klob + rel);                       // Klo
                mma_bf16(cs[2 * nf2],     qh[kc], bk[0], bk[1]);
                mma_bf16(cs[2 * nf2 + 1], qh[kc], bk[2], bk[3]);
            }
        }

        // ---- fused epilogue + PV ----
        const bool diag = (kt == qt);
        const int m0 = warp * 16 + g8;           // local rows m0, m0+8
        const float qs0 = qsq_s[m0], qs1 = qsq_s[m0 + 8];

        #pragma unroll
        for (int kc = 0; kc < 8; kc++) {
            uint32_t ah[4], al[4];
            #pragma unroll
            for (int h = 0; h < 2; h++) {
                const int nf = 2 * kc + h;
                const int n0 = nf * 8 + t2;
                const float2 kk = *(const float2*)&ksq_s[n0];
                float p00 = __expf(fmaf(0.25f, cs[nf][0], -(qs0 + kk.x)));
                float p01 = __expf(fmaf(0.25f, cs[nf][1], -(qs0 + kk.y)));
                float p10 = __expf(fmaf(0.25f, cs[nf][2], -(qs1 + kk.x)));
                float p11 = __expf(fmaf(0.25f, cs[nf][3], -(qs1 + kk.y)));
                if (diag) {
                    if (n0     > m0)     p00 = 0.f;
                    if (n0 + 1 > m0)     p01 = 0.f;
                    if (n0     > m0 + 8) p10 = 0.f;
                    if (n0 + 1 > m0 + 8) p11 = 0.f;
                }
                __nv_bfloat162 h0 = __floats2bfloat162_rn(p00, p01);
                __nv_bfloat162 h1 = __floats2bfloat162_rn(p10, p11);
                float2 f0 = __bfloat1622float2(h0);
                float2 f1 = __bfloat1622float2(h1);
                ah[2 * h]     = b2u(h0);
                ah[2 * h + 1] = b2u(h1);
                al[2 * h]     = b2u(__floats2bfloat162_rn(p00 - f0.x, p01 - f0.y));
                al[2 * h + 1] = b2u(__floats2bfloat162_rn(p10 - f1.x, p11 - f1.y));
            }
            const int key = kc * 16 + vrow;
            #pragma unroll
            for (int df2 = 0; df2 < 4; df2++) {
                uint32_t db = df2 * 32 + vcb;
                uint32_t rel = key * 128 + (((db >> 4) ^ (key & 7)) << 4);
                uint32_t bv[4];
                ldsm4t(bv, vhib + rel);                      // Vhi
                mma_bf16(co[2 * df2],     ah, bv[0], bv[1]);
                mma_bf16(co[2 * df2 + 1], ah, bv[2], bv[3]);
                mma_bf16(co[2 * df2],     al, bv[0], bv[1]);
                mma_bf16(co[2 * df2 + 1], al, bv[2], bv[3]);
                ldsm4t(bv, vhib + 16384 + rel);              // Vlo
                mma_bf16(co[2 * df2],     ah, bv[0], bv[1]);
                mma_bf16(co[2 * df2 + 1], ah, bv[2], bv[3]);
            }
        }
        __syncthreads();
    }

    // ---- write output ----
    const size_t r0 = row0q + warp * 16 + g8;
    const size_t r1 = r0 + 8;
    #pragma unroll
    for (int nf = 0; nf < 8; nf++) {
        const int d = nf * 8 + t2;
        *(float2*)&out[r0 * D_ + d] = make_float2(co[nf][0], co[nf][1]);
        *(float2*)&out[r1 * D_ + d] = make_float2(co[nf][2], co[nf][3]);
    }
}

extern "C" void kernel_launch(void* const* d_in, const int* in_sizes, int n_in,
                              void* d_out, int out_size) {
    const float* q = (const float*)d_in[0];
    const float* k = (const float*)d_in[1];
    const float* v = (const float*)d_in[2];
    float* out = (float*)d_out;

    prep_kernel<<<NBHS / 8, 256>>>(q, k, v);

    cudaFuncSetAttribute(rbf_mma_kernel,
                         cudaFuncAttributeMaxDynamicSharedMemorySize, SMEM_BYTES);
    dim3 grid(S_ / 128, B_ * H_);
    rbf_mma_kernel<<<grid, NT, SMEM_BYTES>>>(out);
}